// round 1
// baseline (speedup 1.0000x reference)
#include <cuda_runtime.h>

#define NN 64
#define PITCH 68
#define NB (NN * PITCH)   // 4352 floats per 64x64 buffer
#define PI_D 3.14159265358979323846

// Circulant taps, duplicated/periodic so index (d + 64) with d in [-63, 64] is in-range.
__device__ float d_G2[160];
__device__ float d_H2[160];

__global__ void init_mats_kernel() {
    int t = threadIdx.x;
    if (t >= 160) return;
    double sg = 1.0, sh = 1.0;
    for (int k = 1; k <= 31; k++) {
        double a = PI_D * (double)k / 64.0;
        sg += 2.0 * cos(a * (2.0 * (double)t + 1.0));
        sh += 2.0 * cos(a * (2.0 * (double)t - 1.0));
    }
    d_G2[t] = (float)(sg / 64.0);
    d_H2[t] = (float)(sh / 128.0);
}

// dst[i'][j] = sum_k Ck[(i'-k)+64] * src[k][j]   (left-multiply by circulant)
__device__ __forceinline__ void mm_left(float* __restrict__ dst,
                                        const float* __restrict__ src,
                                        const float* __restrict__ Ck,
                                        int r0, int c0) {
    float acc[4][4] = {};
    #pragma unroll 2
    for (int k = 0; k < 64; k += 4) {
        float g[8];
        const float* gp = &Ck[r0 - k + 61];   // gp[w] = Ck[r0 - k - 3 + 64 + w]
        #pragma unroll
        for (int w = 0; w < 8; w++) g[w] = gp[w];
        #pragma unroll
        for (int q = 0; q < 4; q++) {
            float4 bv = *(const float4*)&src[(k + q) * PITCH + c0];
            #pragma unroll
            for (int r = 0; r < 4; r++) {
                float a = g[r + 3 - q];        // Ck[(r0+r) - (k+q) + 64]
                acc[r][0] = fmaf(a, bv.x, acc[r][0]);
                acc[r][1] = fmaf(a, bv.y, acc[r][1]);
                acc[r][2] = fmaf(a, bv.z, acc[r][2]);
                acc[r][3] = fmaf(a, bv.w, acc[r][3]);
            }
        }
    }
    #pragma unroll
    for (int r = 0; r < 4; r++)
        *(float4*)&dst[(r0 + r) * PITCH + c0] =
            make_float4(acc[r][0], acc[r][1], acc[r][2], acc[r][3]);
}

// dst[i][m] = sum_k src[i][k] * Ck[(m-k)+64]    (right-multiply by circulant^T)
__device__ __forceinline__ void mm_right(float* __restrict__ dst,
                                         const float* __restrict__ src,
                                         const float* __restrict__ Ck,
                                         int r0, int c0) {
    float acc[4][4] = {};
    #pragma unroll 2
    for (int k = 0; k < 64; k += 4) {
        float h[8];
        const float* hp = &Ck[c0 - k + 61];   // hp[w] = Ck[c0 - k - 3 + 64 + w]
        #pragma unroll
        for (int w = 0; w < 8; w++) h[w] = hp[w];
        #pragma unroll
        for (int r = 0; r < 4; r++) {
            float4 sv = *(const float4*)&src[(r0 + r) * PITCH + k];
            #pragma unroll
            for (int c = 0; c < 4; c++) {
                // src[.][k+q] pairs with Ck[c0+c-(k+q)+64] -> h[c+3-q]
                acc[r][c] = fmaf(sv.x, h[c + 3], acc[r][c]);
                acc[r][c] = fmaf(sv.y, h[c + 2], acc[r][c]);
                acc[r][c] = fmaf(sv.z, h[c + 1], acc[r][c]);
                acc[r][c] = fmaf(sv.w, h[c + 0], acc[r][c]);
            }
        }
    }
    #pragma unroll
    for (int r = 0; r < 4; r++)
        *(float4*)&dst[(r0 + r) * PITCH + c0] =
            make_float4(acc[r][0], acc[r][1], acc[r][2], acc[r][3]);
}

__global__ void __launch_bounds__(256, 2)
uppolyact_kernel(const float* __restrict__ xg,
                 const float* __restrict__ coef,
                 float* __restrict__ outg) {
    extern __shared__ float sm[];
    float* SX = sm;            // x                 (kept for final affine)
    float* S1 = sm + NB;       // M1 = x G^T   -> p_eo
    float* S2 = sm + 2 * NB;   // M2 = G x     -> p_oe -> tmp
    float* S3 = sm + 3 * NB;   // M3 = M2 G^T  -> p_oo -> p_eo H^T
    float* S5 = sm + 4 * NB;   // p_ee
    float* S6 = sm + 5 * NB;   // p_oo H^T  -> H*tmp
    float* Gs = sm + 6 * NB;   // 160
    float* Hs = Gs + 160;      // 160
    float* rs  = Hs + 160;     // 64: sum_i (-1)^i x[i][j]
    float* cs  = rs + 64;      // 64: sum_j (-1)^j x[i][j]
    float* rs1 = cs + 64;      // 64: sum_i (-1)^i M1[i][j]
    float* cs2 = rs1 + 64;     // 64: sum_j (-1)^j M2[i][j]
    float* tsp = cs2 + 64;     // 1

    const int tid = threadIdx.x;
    const int tx = tid & 15, ty = tid >> 4;
    const int r0 = ty << 2, c0 = tx << 2;
    const float* xin = xg + (size_t)blockIdx.x * 4096;
    float* outp = outg + (size_t)blockIdx.x * 4096;

    if (tid < 160) { Gs[tid] = d_G2[tid]; Hs[tid] = d_H2[tid]; }

    // Load image (contiguous 64x64) into padded smem
    #pragma unroll
    for (int i = tid; i < 1024; i += 256) {
        float4 v = ((const float4*)xin)[i];
        *(float4*)&SX[(i >> 4) * PITCH + ((i & 15) << 2)] = v;
    }
    __syncthreads();

    // M2 = G x (rows), M1 = x G^T (cols) — both read only SX
    mm_left (S2, SX, Gs, r0, c0);
    mm_right(S1, SX, Gs, r0, c0);
    __syncthreads();

    // Alternating-sign reductions for the rank-1 (even-phase) corrections
    {
        int t = tid & 63;
        float s = 0.f;
        if (tid < 64) {
            for (int i = 0; i < 64; i += 2) s += SX[i * PITCH + t] - SX[(i + 1) * PITCH + t];
            rs[t] = s;
        } else if (tid < 128) {
            const float* row = &SX[t * PITCH];
            for (int j = 0; j < 64; j += 2) s += row[j] - row[j + 1];
            cs[t] = s;
        } else if (tid < 192) {
            for (int i = 0; i < 64; i += 2) s += S1[i * PITCH + t] - S1[(i + 1) * PITCH + t];
            rs1[t] = s;
        } else {
            const float* row = &S2[t * PITCH];
            for (int j = 0; j < 64; j += 2) s += row[j] - row[j + 1];
            cs2[t] = s;
        }
    }
    __syncthreads();

    if (tid == 0) {
        float s = 0.f;
        for (int j = 0; j < 64; j += 2) s += rs[j] - rs[j + 1];
        tsp[0] = s;
    }
    // M3 = M2 G^T  (both-odd phase)
    mm_right(S3, S2, Gs, r0, c0);
    __syncthreads();

    // Apply even-phase corrections and square all four polyphases
    {
        const float ts = tsp[0];
        const float inv64 = 1.0f / 64.0f;
        const float inv4096 = inv64 * inv64;
        #pragma unroll
        for (int r = 0; r < 4; r++) {
            int i = r0 + r;
            float sgni = (i & 1) ? -1.f : 1.f;
            float csv  = cs[i]  * inv64;
            float cs2v = cs2[i] * inv64;
            #pragma unroll
            for (int c = 0; c < 4; c++) {
                int j = c0 + c;
                float sgnj = (j & 1) ? -1.f : 1.f;
                int idx = i * PITCH + j;
                float vee = SX[idx] + sgni * rs[j] * inv64 + sgnj * csv
                          + sgni * sgnj * ts * inv4096;
                S5[idx] = vee * vee;                            // p_ee
                float veo = S1[idx] + sgni * rs1[j] * inv64;
                S1[idx] = veo * veo;                            // p_eo
                float voe = S2[idx] + sgnj * cs2v;
                S2[idx] = voe * voe;                            // p_oe
                float voo = S3[idx];
                S3[idx] = voo * voo;                            // p_oo
            }
        }
    }
    __syncthreads();

    // S6 = p_oo H^T
    mm_right(S6, S3, Hs, r0, c0);
    __syncthreads();

    // tmp: S2 = 0.5*p_oe + p_oo H^T
    #pragma unroll
    for (int r = 0; r < 4; r++) {
        int base = (r0 + r) * PITCH + c0;
        float4 a = *(float4*)&S2[base];
        float4 b = *(float4*)&S6[base];
        *(float4*)&S2[base] = make_float4(0.5f * a.x + b.x, 0.5f * a.y + b.y,
                                          0.5f * a.z + b.z, 0.5f * a.w + b.w);
    }
    __syncthreads();

    // S6 = H * tmp ;  S3 = p_eo H^T
    mm_left (S6, S2, Hs, r0, c0);
    mm_right(S3, S1, Hs, r0, c0);
    __syncthreads();

    // out = c0 + c1*x + c2*(0.25*p_ee + 0.5*(p_eo H^T) + H*tmp)
    {
        const float k0 = coef[0], k1 = coef[1], k2 = coef[2];
        #pragma unroll
        for (int r = 0; r < 4; r++) {
            int i = r0 + r;
            int base = i * PITCH + c0;
            float4 xv = *(float4*)&SX[base];
            float4 ee = *(float4*)&S5[base];
            float4 eo = *(float4*)&S3[base];
            float4 ob = *(float4*)&S6[base];
            float4 o;
            o.x = k0 + k1 * xv.x + k2 * (0.25f * ee.x + 0.5f * eo.x + ob.x);
            o.y = k0 + k1 * xv.y + k2 * (0.25f * ee.y + 0.5f * eo.y + ob.y);
            o.z = k0 + k1 * xv.z + k2 * (0.25f * ee.z + 0.5f * eo.z + ob.z);
            o.w = k0 + k1 * xv.w + k2 * (0.25f * ee.w + 0.5f * eo.w + ob.w);
            *(float4*)&outp[i * 64 + c0] = o;
        }
    }
}

extern "C" void kernel_launch(void* const* d_in, const int* in_sizes, int n_in,
                              void* d_out, int out_size) {
    const float* x    = (const float*)d_in[0];
    const float* coef = (const float*)d_in[1];
    float* out = (float*)d_out;

    init_mats_kernel<<<1, 160>>>();

    int smem_bytes = (6 * NB + 640) * (int)sizeof(float);  // ~107 KB
    cudaFuncSetAttribute(uppolyact_kernel,
                         cudaFuncAttributeMaxDynamicSharedMemorySize, smem_bytes);

    int nimg = in_sizes[0] / 4096;   // 32*128 = 4096 images of 64x64
    uppolyact_kernel<<<nimg, 256, smem_bytes>>>(x, coef, out);
}